// round 3
// baseline (speedup 1.0000x reference)
#include <cuda_runtime.h>
#include <math_constants.h>

#define NTOT 4096
#define MTOT 4096
#define NP 4                      // packed f32x2 pairs per thread -> 8 pred points
#define TPB 256
#define N_PER_BLOCK (TPB * NP * 2)   // 2048 pred points per block
#define MCHUNK 512                   // targets per block (smem tile)

// scratch (no allocations allowed)
__device__ int   g_min[32 * NTOT];   // bit patterns of nonneg float d2, combined via atomicMin
__device__ float g_bsum[512];        // per-block partial sums of sqrt(d2)

// ---- packed f32x2 helpers (sm_100+; FFMA2 only reachable via PTX) ----
__device__ __forceinline__ unsigned long long fma2(unsigned long long a,
                                                   unsigned long long b,
                                                   unsigned long long c) {
    unsigned long long d;
    asm("fma.rn.f32x2 %0, %1, %2, %3;" : "=l"(d) : "l"(a), "l"(b), "l"(c));
    return d;
}
__device__ __forceinline__ unsigned long long pack2(float lo, float hi) {
    unsigned long long r;
    asm("mov.b64 %0, {%1, %2};" : "=l"(r) : "f"(lo), "f"(hi));
    return r;
}
__device__ __forceinline__ float2 unpack2(unsigned long long v) {
    float2 r;
    asm("mov.b64 {%0, %1}, %2;" : "=f"(r.x), "=f"(r.y) : "l"(v));
    return r;
}

// ---- kernel 0: init min scratch to +inf ----
__global__ void emd_init() {
    g_min[blockIdx.x * 256 + threadIdx.x] = 0x7f800000;  // +inf
}

// ---- kernel 1: main pairwise-min ----
// grid: (NTOT/N_PER_BLOCK, MTOT/MCHUNK, B), block: TPB
__global__ __launch_bounds__(TPB)
void emd_min_kernel(const float* __restrict__ pred, const float* __restrict__ target) {
    const int b  = blockIdx.z;
    const int nb = blockIdx.x * N_PER_BLOCK + threadIdx.x * (NP * 2);
    const int mb = blockIdx.y * MCHUNK;

    // per target: (a,a),(b,b),(c,c),(d,d) pre-duplicated for packed fma
    __shared__ ulonglong2 sT[MCHUNK * 2];   // 16 KB

    for (int i = threadIdx.x; i < MCHUNK; i += TPB) {
        const float* t = target + ((size_t)b * MTOT + (mb + i)) * 3;
        float tx = t[0], ty = t[1], tz = t[2];
        float ca = -2.0f * tx, cb = -2.0f * ty, cc = -2.0f * tz;
        float cd = tx * tx + ty * ty + tz * tz;
        sT[i * 2 + 0] = make_ulonglong2(pack2(ca, ca), pack2(cb, cb));
        sT[i * 2 + 1] = make_ulonglong2(pack2(cc, cc), pack2(cd, cd));
    }

    // load this thread's 8 pred points (24 contiguous floats, 16B-aligned)
    const float* p = pred + ((size_t)b * NTOT + nb) * 3;
    float f[24];
#pragma unroll
    for (int i = 0; i < 6; i++) {
        float4 v = reinterpret_cast<const float4*>(p)[i];
        f[i * 4 + 0] = v.x; f[i * 4 + 1] = v.y; f[i * 4 + 2] = v.z; f[i * 4 + 3] = v.w;
    }
    unsigned long long PX[NP], PY[NP], PZ[NP];
#pragma unroll
    for (int k = 0; k < NP; k++) {
        PX[k] = pack2(f[6 * k + 0], f[6 * k + 3]);
        PY[k] = pack2(f[6 * k + 1], f[6 * k + 4]);
        PZ[k] = pack2(f[6 * k + 2], f[6 * k + 5]);
    }

    float2 vmin[NP];
#pragma unroll
    for (int k = 0; k < NP; k++) vmin[k] = make_float2(CUDART_INF_F, CUDART_INF_F);

    __syncthreads();

    // inner loop: per target, per packed pair: v = a*px + b*py + c*pz + d  (3 FFMA2)
#pragma unroll 4
    for (int m = 0; m < MCHUNK; m++) {
        ulonglong2 q0 = sT[m * 2 + 0];   // (a,a),(b,b)
        ulonglong2 q1 = sT[m * 2 + 1];   // (c,c),(d,d)
#pragma unroll
        for (int k = 0; k < NP; k++) {
            unsigned long long v = fma2(q1.x, PZ[k], q1.y);
            v = fma2(q0.y, PY[k], v);
            v = fma2(q0.x, PX[k], v);
            float2 vf = unpack2(v);
            vmin[k].x = fminf(vmin[k].x, vf.x);
            vmin[k].y = fminf(vmin[k].y, vf.y);
        }
    }

    // finalize: d2 = max(vmin + |p|^2, 0); combine across M-chunks with int atomicMin
#pragma unroll
    for (int k = 0; k < NP; k++) {
#pragma unroll
        for (int h = 0; h < 2; h++) {
            float px = f[6 * k + 3 * h + 0];
            float py = f[6 * k + 3 * h + 1];
            float pz = f[6 * k + 3 * h + 2];
            float p2 = px * px + py * py + pz * pz;
            float vm = h ? vmin[k].y : vmin[k].x;
            float d2 = fmaxf(vm + p2, 0.0f);
            atomicMin(&g_min[b * NTOT + nb + 2 * k + h], __float_as_int(d2));
        }
    }
}

// ---- kernel 2: sqrt + per-block sum (deterministic) ----
__global__ void emd_reduce1() {
    __shared__ float ss[256];
    int i = blockIdx.x * 512 + threadIdx.x;
    float s = sqrtf(__int_as_float(g_min[i])) + sqrtf(__int_as_float(g_min[i + 256]));
    ss[threadIdx.x] = s;
    __syncthreads();
#pragma unroll
    for (int o = 128; o > 0; o >>= 1) {
        if (threadIdx.x < o) ss[threadIdx.x] += ss[threadIdx.x + o];
        __syncthreads();
    }
    if (threadIdx.x == 0) g_bsum[blockIdx.x] = ss[0];
}

// ---- kernel 3: final sum + mean ----
__global__ void emd_reduce2(float* out, int nblocks, float inv_count) {
    __shared__ float ss[256];
    float s = 0.0f;
    for (int i = threadIdx.x; i < nblocks; i += 256) s += g_bsum[i];
    ss[threadIdx.x] = s;
    __syncthreads();
#pragma unroll
    for (int o = 128; o > 0; o >>= 1) {
        if (threadIdx.x < o) ss[threadIdx.x] += ss[threadIdx.x + o];
        __syncthreads();
    }
    if (threadIdx.x == 0) out[0] = ss[0] * inv_count;
}

extern "C" void kernel_launch(void* const* d_in, const int* in_sizes, int n_in,
                              void* d_out, int out_size) {
    const float* pred   = (const float*)d_in[0];
    const float* target = (const float*)d_in[1];
    const int B = in_sizes[0] / (NTOT * 3);        // 32
    const int total = B * NTOT;                    // 131072

    emd_init<<<total / 256, 256>>>();

    dim3 g1(NTOT / N_PER_BLOCK, MTOT / MCHUNK, B); // (2, 8, 32) = 512 blocks
    emd_min_kernel<<<g1, TPB>>>(pred, target);

    int rb = total / 512;                          // 256 reduce blocks
    emd_reduce1<<<rb, 256>>>();
    emd_reduce2<<<1, 256>>>((float*)d_out, rb, 1.0f / (float)total);
}

// round 6
// speedup vs baseline: 1.0584x; 1.0584x over previous
#include <cuda_runtime.h>
#include <math_constants.h>

#define NTOT 4096
#define MTOT 4096
#define NP 4                         // packed f32x2 pairs per thread -> 8 pred points
#define TPB 256
#define N_PER_BLOCK (TPB * NP * 2)   // 2048 pred points per block
#define MCHUNK 256                   // targets per block (smem tile)

// scratch (no allocations allowed)
__device__ int   g_min[32 * NTOT];   // bit patterns of nonneg float d2, combined via atomicMin
__device__ float g_bsum[512];        // per-block partial sums of sqrt(d2)

// ---- packed f32x2 helpers (sm_100+; FFMA2 only reachable via PTX) ----
__device__ __forceinline__ unsigned long long fma2(unsigned long long a,
                                                   unsigned long long b,
                                                   unsigned long long c) {
    unsigned long long d;
    asm("fma.rn.f32x2 %0, %1, %2, %3;" : "=l"(d) : "l"(a), "l"(b), "l"(c));
    return d;
}
__device__ __forceinline__ unsigned long long pack2(float lo, float hi) {
    unsigned long long r;
    asm("mov.b64 %0, {%1, %2};" : "=l"(r) : "f"(lo), "f"(hi));
    return r;
}
__device__ __forceinline__ float2 unpack2(unsigned long long v) {
    float2 r;
    asm("mov.b64 {%0, %1}, %2;" : "=f"(r.x), "=f"(r.y) : "l"(v));
    return r;
}

// ---- kernel 0: init min scratch to +inf ----
__global__ void emd_init() {
    g_min[blockIdx.x * 256 + threadIdx.x] = 0x7f800000;  // +inf
}

// ---- kernel 1: main pairwise-min ----
// grid: (NTOT/N_PER_BLOCK, MTOT/MCHUNK, B) = (2, 16, 32) = 1024 blocks, block: TPB
__global__ void __launch_bounds__(TPB, 4)
emd_min_kernel(const float* __restrict__ pred, const float* __restrict__ target) {
    const int b  = blockIdx.z;
    const int nb = blockIdx.x * N_PER_BLOCK + threadIdx.x * (NP * 2);
    const int mb = blockIdx.y * MCHUNK;

    // per target: (a,a),(b,b) and (c,c),(d,d) pre-duplicated for packed fma
    __shared__ ulonglong2 sT[MCHUNK * 2];   // 8 KB

    {
        // exactly one target per thread (MCHUNK == TPB)
        const int i = threadIdx.x;
        const float* t = target + ((size_t)b * MTOT + (mb + i)) * 3;
        float tx = t[0], ty = t[1], tz = t[2];
        float ca = -2.0f * tx, cb = -2.0f * ty, cc = -2.0f * tz;
        float cd = fmaf(tx, tx, fmaf(ty, ty, tz * tz));
        sT[i * 2 + 0] = make_ulonglong2(pack2(ca, ca), pack2(cb, cb));
        sT[i * 2 + 1] = make_ulonglong2(pack2(cc, cc), pack2(cd, cd));
    }

    // load this thread's 8 pred points (24 contiguous floats) straight into
    // packed registers; no persistent scalar copy (register diet for occ=4).
    unsigned long long PX[NP], PY[NP], PZ[NP];
    {
        const float4* p4 = reinterpret_cast<const float4*>(
            pred + ((size_t)b * NTOT + nb) * 3);
        float4 v[6];
#pragma unroll
        for (int i = 0; i < 6; i++) v[i] = p4[i];
        const float* f = reinterpret_cast<const float*>(v);
#pragma unroll
        for (int k = 0; k < NP; k++) {
            PX[k] = pack2(f[6 * k + 0], f[6 * k + 3]);
            PY[k] = pack2(f[6 * k + 1], f[6 * k + 4]);
            PZ[k] = pack2(f[6 * k + 2], f[6 * k + 5]);
        }
    }

    float2 vmin[NP];
#pragma unroll
    for (int k = 0; k < NP; k++) vmin[k] = make_float2(CUDART_INF_F, CUDART_INF_F);

    __syncthreads();

    // inner loop: per target, per packed pair: v = a*px + b*py + c*pz + d  (3 FFMA2)
#pragma unroll 2
    for (int m = 0; m < MCHUNK; m++) {
        ulonglong2 q0 = sT[m * 2 + 0];   // (a,a),(b,b)  broadcast
        ulonglong2 q1 = sT[m * 2 + 1];   // (c,c),(d,d)  broadcast
#pragma unroll
        for (int k = 0; k < NP; k++) {
            unsigned long long v = fma2(q1.x, PZ[k], q1.y);
            v = fma2(q0.y, PY[k], v);
            v = fma2(q0.x, PX[k], v);
            float2 vf = unpack2(v);
            vmin[k].x = fminf(vmin[k].x, vf.x);
            vmin[k].y = fminf(vmin[k].y, vf.y);
        }
    }

    // finalize: d2 = max(vmin + |p|^2, 0); combine across M-chunks with int atomicMin
    int* gm = &g_min[b * NTOT + nb];
#pragma unroll
    for (int k = 0; k < NP; k++) {
        float2 x = unpack2(PX[k]);
        float2 y = unpack2(PY[k]);
        float2 z = unpack2(PZ[k]);
        float p2a = fmaf(x.x, x.x, fmaf(y.x, y.x, z.x * z.x));
        float p2b = fmaf(x.y, x.y, fmaf(y.y, y.y, z.y * z.y));
        float d2a = fmaxf(vmin[k].x + p2a, 0.0f);
        float d2b = fmaxf(vmin[k].y + p2b, 0.0f);
        atomicMin(&gm[2 * k + 0], __float_as_int(d2a));
        atomicMin(&gm[2 * k + 1], __float_as_int(d2b));
    }
}

// ---- kernel 2: sqrt + per-block sum (deterministic) ----
__global__ void emd_reduce1() {
    __shared__ float ss[256];
    int i = blockIdx.x * 512 + threadIdx.x;
    float s = sqrtf(__int_as_float(g_min[i])) + sqrtf(__int_as_float(g_min[i + 256]));
    ss[threadIdx.x] = s;
    __syncthreads();
#pragma unroll
    for (int o = 128; o > 0; o >>= 1) {
        if (threadIdx.x < o) ss[threadIdx.x] += ss[threadIdx.x + o];
        __syncthreads();
    }
    if (threadIdx.x == 0) g_bsum[blockIdx.x] = ss[0];
}

// ---- kernel 3: final sum + mean ----
__global__ void emd_reduce2(float* out, int nblocks, float inv_count) {
    __shared__ float ss[256];
    float s = 0.0f;
    for (int i = threadIdx.x; i < nblocks; i += 256) s += g_bsum[i];
    ss[threadIdx.x] = s;
    __syncthreads();
#pragma unroll
    for (int o = 128; o > 0; o >>= 1) {
        if (threadIdx.x < o) ss[threadIdx.x] += ss[threadIdx.x + o];
        __syncthreads();
    }
    if (threadIdx.x == 0) out[0] = ss[0] * inv_count;
}

extern "C" void kernel_launch(void* const* d_in, const int* in_sizes, int n_in,
                              void* d_out, int out_size) {
    const float* pred   = (const float*)d_in[0];
    const float* target = (const float*)d_in[1];
    const int B = in_sizes[0] / (NTOT * 3);        // 32
    const int total = B * NTOT;                    // 131072

    emd_init<<<total / 256, 256>>>();

    dim3 g1(NTOT / N_PER_BLOCK, MTOT / MCHUNK, B); // (2, 16, 32) = 1024 blocks
    emd_min_kernel<<<g1, TPB>>>(pred, target);

    int rb = total / 512;                          // 256 reduce blocks
    emd_reduce1<<<rb, 256>>>();
    emd_reduce2<<<1, 256>>>((float*)d_out, rb, 1.0f / (float)total);
}